// round 9
// baseline (speedup 1.0000x reference)
#include <cuda_runtime.h>
#include <cstdint>

#define B_  8
#define C_  19
#define H_  512
#define W_  512
#define PLANE (H_*W_)          // 262144
#define BC (B_*C_)             // 152

// adjusted: [B,C,64,64]
__device__ float g_adjusted[BC * 64 * 64];

// ---------------------------------------------------------------------------
// Kernel 1 (per batch): argmax over C=19 + 8x8 histogram /64.
// Grid (2 col-halves, 64 strips), 256 threads: t&63 = col quad (within the
// 256-col half), t>>6 = row group (2 rows). Default-policy loads: x[b] must
// stay L2-resident for modulate(b).
// ---------------------------------------------------------------------------
__global__ __launch_bounds__(256) void argmax_pool_kernel(const float* __restrict__ x,
                                                          int b)
{
    const int half  = blockIdx.x;          // 0..1
    const int strip = blockIdx.y;          // 0..63
    const int t     = threadIdx.x;
    const int cq    = t & 63;              // col quad in half (0..63)
    const int rg    = t >> 6;              // row group (0..3), 2 rows each

    __shared__ int hist[32][20];           // 32 blocks x 19 channels (+pad)
    for (int i = t; i < 32 * 20; i += 256) ((int*)hist)[i] = 0;
    __syncthreads();

    const float* xb = x + (size_t)b * C_ * PLANE
                        + ((size_t)strip * 8 + rg * 2) * W_
                        + half * 256 + cq * 4;
    const int blk = cq >> 1;               // 8x8 block within half (0..31)

    #pragma unroll
    for (int r = 0; r < 2; r++) {
        const float* row = xb + r * W_;
        float4 bv = *(const float4*)row;
        int bx = 0, by = 0, bz = 0, bw = 0;
        #pragma unroll
        for (int c = 1; c < C_; c++) {
            float4 v = *(const float4*)(row + (size_t)c * PLANE);
            if (v.x > bv.x) { bv.x = v.x; bx = c; }
            if (v.y > bv.y) { bv.y = v.y; by = c; }
            if (v.z > bv.z) { bv.z = v.z; bz = c; }
            if (v.w > bv.w) { bv.w = v.w; bw = c; }
        }
        atomicAdd(&hist[blk][bx], 1);
        atomicAdd(&hist[blk][by], 1);
        atomicAdd(&hist[blk][bz], 1);
        atomicAdd(&hist[blk][bw], 1);
    }
    __syncthreads();

    for (int i = t; i < 32 * C_; i += 256) {
        int j = i / C_, c = i % C_;
        g_adjusted[((size_t)(b * C_ + c) * 64 + strip) * 64 + half * 32 + j] =
            (float)hist[j][c] * (1.0f / 64.0f);
    }
}

// ---------------------------------------------------------------------------
// Kernel 2 (per batch): fused einsum + fold + epilogue, R6 core.
// 16 CTAs per plane (304 CTAs/batch). CTA q handles tile rows q*2, q*2+1
// (global tiles q*64 .. q*64+63, contiguous). 4 m-groups: row = mgrp>>1,
// col half = mgrp&1, 16 tiles each. x via __ldcg (L2 hits from argmax(b)),
// outputs via __stcs (evict-first: don't pollute L2).
// ---------------------------------------------------------------------------
#define CPPB 16                // CTAs per plane

__global__ __launch_bounds__(256, 2) void modulate_kernel(
    const float* __restrict__ x,
    const float* __restrict__ attn,
    float* __restrict__ out_y,
    float* __restrict__ out_c,
    int b)
{
    const int bcl  = blockIdx.x >> 4;      // 0..18
    const int q    = blockIdx.x & 15;      // 0..15
    const int bc   = b * C_ + bcl;
    const int tid  = threadIdx.x;
    const int mgrp = tid >> 6;             // 0..3
    const int quad = tid & 63;
    const int py   = quad >> 2;            // 0..15
    const int px0  = (quad & 3) << 2;      // 0,4,8,12

    __shared__ float4 sm_attn[64 * 4];     // 64 tiles x 16 floats = 4KB

    const float* adjc = g_adjusted + (size_t)bc * 4096;
    float4 pr[16];
    #pragma unroll
    for (int pi = 0; pi < 4; pi++)
        #pragma unroll
        for (int pj = 0; pj < 4; pj++)
            pr[pi * 4 + pj] =
                *(const float4*)(adjc + (pi * 16 + py) * 64 + pj * 16 + px0);

    // stage attn rows for this CTA's 64 contiguous tiles (m = q*64 ..)
    const float4* src = (const float4*)(attn + (size_t)bc * 1024 * 16) + q * 64 * 4;
    for (int i = tid; i < 64 * 4; i += 256) sm_attn[i] = src[i];
    __syncthreads();

    const float* xp = x + (size_t)bc * PLANE;
    float*       yp = out_y + (size_t)bc * PLANE;
    float*       cp = out_c + (size_t)bc * PLANE;

    const int mh   = q * 2 + (mgrp >> 1);        // tile row (0..31)
    const int ch   = mgrp & 1;                   // col half of tile row
    const int h    = mh * 16 + py;
    const size_t base = (size_t)h * W_ + ch * 256 + px0;
    const int mlbase = (mgrp >> 1) * 32 + ch * 16;   // local tile index base

    #pragma unroll 1
    for (int ib = 0; ib < 16; ib += 4) {
        const size_t pix0 = base + (size_t)ib * 16;

        // 4 front-batched loads (MLP_p1 = 4), L2-preferring
        float4 xq0 = __ldcg((const float4*)(xp + pix0));
        float4 xq1 = __ldcg((const float4*)(xp + pix0 + 16));
        float4 xq2 = __ldcg((const float4*)(xp + pix0 + 32));
        float4 xq3 = __ldcg((const float4*)(xp + pix0 + 48));

        #pragma unroll
        for (int j = 0; j < 4; j++) {
            const float4 cur = (j == 0) ? xq0 : (j == 1) ? xq1 : (j == 2) ? xq2 : xq3;
            const size_t pix = pix0 + (size_t)j * 16;
            const int mloc = mlbase + ib + j;

            float4 c4 = make_float4(0.f, 0.f, 0.f, 0.f);
            #pragma unroll
            for (int g = 0; g < 4; g++) {
                float4 a4 = sm_attn[mloc * 4 + g];
                c4.x = fmaf(a4.x, pr[g*4+0].x, c4.x);
                c4.y = fmaf(a4.x, pr[g*4+0].y, c4.y);
                c4.z = fmaf(a4.x, pr[g*4+0].z, c4.z);
                c4.w = fmaf(a4.x, pr[g*4+0].w, c4.w);
                c4.x = fmaf(a4.y, pr[g*4+1].x, c4.x);
                c4.y = fmaf(a4.y, pr[g*4+1].y, c4.y);
                c4.z = fmaf(a4.y, pr[g*4+1].z, c4.z);
                c4.w = fmaf(a4.y, pr[g*4+1].w, c4.w);
                c4.x = fmaf(a4.z, pr[g*4+2].x, c4.x);
                c4.y = fmaf(a4.z, pr[g*4+2].y, c4.y);
                c4.z = fmaf(a4.z, pr[g*4+2].z, c4.z);
                c4.w = fmaf(a4.z, pr[g*4+2].w, c4.w);
                c4.x = fmaf(a4.w, pr[g*4+3].x, c4.x);
                c4.y = fmaf(a4.w, pr[g*4+3].y, c4.y);
                c4.z = fmaf(a4.w, pr[g*4+3].z, c4.z);
                c4.w = fmaf(a4.w, pr[g*4+3].w, c4.w);
            }

            float4 y2;
            float tx = 1.f + c4.x; y2.x = cur.x * tx * tx;
            float ty = 1.f + c4.y; y2.y = cur.y * ty * ty;
            float tz = 1.f + c4.z; y2.z = cur.z * tz * tz;
            float tw = 1.f + c4.w; y2.w = cur.w * tw * tw;

            __stcs((float4*)(yp + pix), y2);
            __stcs((float4*)(cp + pix), c4);
        }
    }
}

extern "C" void kernel_launch(void* const* d_in, const int* in_sizes, int n_in,
                              void* d_out, int out_size)
{
    const float* x    = (const float*)d_in[0];
    const float* attn = (const float*)d_in[1];
    float* out_y = (float*)d_out;
    float* out_c = (float*)d_out + (size_t)BC * PLANE;

    for (int b = 0; b < B_; b++) {
        argmax_pool_kernel<<<dim3(2, 64), 256>>>(x, b);
        modulate_kernel<<<C_ * CPPB, 256>>>(x, attn, out_y, out_c, b);
    }
}

// round 11
// speedup vs baseline: 1.0681x; 1.0681x over previous
#include <cuda_runtime.h>
#include <cstdint>

#define B_  8
#define C_  19
#define H_  512
#define W_  512
#define PLANE (H_*W_)          // 262144
#define BC (B_*C_)             // 152

#define NCTA 296               // 2 CTAs/SM on 148+ SMs: all co-resident
#define N_ITEMS 3456           // 8*(128 argmax + 304 modulate)

__device__ float g_adjusted[BC * 4096];
__device__ int   g_done[B_];

// Segment schedule with 1-batch lookahead: A0,A1,M0,A2,M1,...,A7,M6,M7
__constant__ int c_seg_start[17] = {0,128,256,560,688,992,1120,1424,1552,
                                    1856,1984,2288,2416,2720,2848,3152,3456};
__constant__ int c_seg_type[16] = {0,0,1,0,1,0,1,0,1,0,1,0,1,0,1,1};
__constant__ int c_seg_b[16]    = {0,1,0,2,1,3,2,4,3,5,4,6,5,7,6,7};

__global__ void init_kernel() {
    if (threadIdx.x < B_) g_done[threadIdx.x] = 0;
}

// ---------------------------------------------------------------------------
// Argmax work unit: batch b, u in [0,128): half = u&1, strip = u>>1.
// 256 threads: t&63 = col quad within 256-col half, t>>6 = 2-row group.
// Default-policy loads keep x[b] L2-resident for the modulate units.
// ---------------------------------------------------------------------------
__device__ __forceinline__ void argmax_unit(const float* __restrict__ x,
                                            int b, int u, char* smem_raw)
{
    int (*hist)[20] = (int(*)[20])smem_raw;    // 32 x 20 ints = 2560B
    const int t     = threadIdx.x;
    const int half  = u & 1;
    const int strip = u >> 1;
    const int cq    = t & 63;
    const int rg    = t >> 6;

    for (int i = t; i < 32 * 20; i += 256) ((int*)hist)[i] = 0;
    __syncthreads();

    const float* xb = x + (size_t)b * C_ * PLANE
                        + ((size_t)strip * 8 + rg * 2) * W_
                        + half * 256 + cq * 4;
    const int blk = cq >> 1;

    #pragma unroll
    for (int r = 0; r < 2; r++) {
        const float* row = xb + r * W_;
        float4 bv = *(const float4*)row;
        int bx = 0, by = 0, bz = 0, bw = 0;
        #pragma unroll
        for (int c = 1; c < C_; c++) {
            float4 v = *(const float4*)(row + (size_t)c * PLANE);
            if (v.x > bv.x) { bv.x = v.x; bx = c; }
            if (v.y > bv.y) { bv.y = v.y; by = c; }
            if (v.z > bv.z) { bv.z = v.z; bz = c; }
            if (v.w > bv.w) { bv.w = v.w; bw = c; }
        }
        atomicAdd(&hist[blk][bx], 1);
        atomicAdd(&hist[blk][by], 1);
        atomicAdd(&hist[blk][bz], 1);
        atomicAdd(&hist[blk][bw], 1);
    }
    __syncthreads();

    for (int i = t; i < 32 * C_; i += 256) {
        int j = i / C_, c = i % C_;
        g_adjusted[((size_t)(b * C_ + c) * 64 + strip) * 64 + half * 32 + j] =
            (float)hist[j][c] * (1.0f / 64.0f);
    }

    // release: make writes visible, then signal completion
    __threadfence();
    __syncthreads();
    if (t == 0) atomicAdd(&g_done[b], 1);
}

// ---------------------------------------------------------------------------
// Modulate work unit: batch b, v in [0,304): bcl = v>>4, q = v&15.
// R6/R9 core: pr[16] in regs (__ldcg), attn in smem, 4 front-batched LDG.128.
// ---------------------------------------------------------------------------
__device__ __forceinline__ void modulate_unit(const float* __restrict__ x,
                                              const float* __restrict__ attn,
                                              float* __restrict__ out_y,
                                              float* __restrict__ out_c,
                                              int b, int v, char* smem_raw)
{
    float4* sm_attn = (float4*)smem_raw;       // 64 tiles x 16 floats = 4KB
    const int tid  = threadIdx.x;
    const int bcl  = v >> 4;                   // 0..18
    const int q    = v & 15;                   // 0..15
    const int bc   = b * C_ + bcl;
    const int mgrp = tid >> 6;
    const int quad = tid & 63;
    const int py   = quad >> 2;
    const int px0  = (quad & 3) << 2;

    // stage attn while (possibly) waiting on the dependency
    const float4* src = (const float4*)(attn + (size_t)bc * 1024 * 16) + q * 64 * 4;
    for (int i = tid; i < 64 * 4; i += 256) sm_attn[i] = src[i];

    // acquire: wait until all 128 argmax units of batch b completed
    if (tid == 0) {
        while (((volatile int*)g_done)[b] < 128) __nanosleep(64);
        __threadfence();
    }
    __syncthreads();

    const float* adjc = g_adjusted + (size_t)bc * 4096;
    float4 pr[16];
    #pragma unroll
    for (int pi = 0; pi < 4; pi++)
        #pragma unroll
        for (int pj = 0; pj < 4; pj++)
            pr[pi * 4 + pj] =
                __ldcg((const float4*)(adjc + (pi * 16 + py) * 64 + pj * 16 + px0));

    const float* xp = x + (size_t)bc * PLANE;
    float*       yp = out_y + (size_t)bc * PLANE;
    float*       cp = out_c + (size_t)bc * PLANE;

    const int mh   = q * 2 + (mgrp >> 1);
    const int ch   = mgrp & 1;
    const int h    = mh * 16 + py;
    const size_t base = (size_t)h * W_ + ch * 256 + px0;
    const int mlbase = (mgrp >> 1) * 32 + ch * 16;

    #pragma unroll 1
    for (int ib = 0; ib < 16; ib += 4) {
        const size_t pix0 = base + (size_t)ib * 16;

        float4 xq0 = __ldcg((const float4*)(xp + pix0));
        float4 xq1 = __ldcg((const float4*)(xp + pix0 + 16));
        float4 xq2 = __ldcg((const float4*)(xp + pix0 + 32));
        float4 xq3 = __ldcg((const float4*)(xp + pix0 + 48));

        #pragma unroll
        for (int j = 0; j < 4; j++) {
            const float4 cur = (j == 0) ? xq0 : (j == 1) ? xq1 : (j == 2) ? xq2 : xq3;
            const size_t pix = pix0 + (size_t)j * 16;
            const int mloc = mlbase + ib + j;

            float4 c4 = make_float4(0.f, 0.f, 0.f, 0.f);
            #pragma unroll
            for (int g = 0; g < 4; g++) {
                float4 a4 = sm_attn[mloc * 4 + g];
                c4.x = fmaf(a4.x, pr[g*4+0].x, c4.x);
                c4.y = fmaf(a4.x, pr[g*4+0].y, c4.y);
                c4.z = fmaf(a4.x, pr[g*4+0].z, c4.z);
                c4.w = fmaf(a4.x, pr[g*4+0].w, c4.w);
                c4.x = fmaf(a4.y, pr[g*4+1].x, c4.x);
                c4.y = fmaf(a4.y, pr[g*4+1].y, c4.y);
                c4.z = fmaf(a4.y, pr[g*4+1].z, c4.z);
                c4.w = fmaf(a4.y, pr[g*4+1].w, c4.w);
                c4.x = fmaf(a4.z, pr[g*4+2].x, c4.x);
                c4.y = fmaf(a4.z, pr[g*4+2].y, c4.y);
                c4.z = fmaf(a4.z, pr[g*4+2].z, c4.z);
                c4.w = fmaf(a4.z, pr[g*4+2].w, c4.w);
                c4.x = fmaf(a4.w, pr[g*4+3].x, c4.x);
                c4.y = fmaf(a4.w, pr[g*4+3].y, c4.y);
                c4.z = fmaf(a4.w, pr[g*4+3].z, c4.z);
                c4.w = fmaf(a4.w, pr[g*4+3].w, c4.w);
            }

            float4 y2;
            float tx = 1.f + c4.x; y2.x = cur.x * tx * tx;
            float ty = 1.f + c4.y; y2.y = cur.y * ty * ty;
            float tz = 1.f + c4.z; y2.z = cur.z * tz * tz;
            float tw = 1.f + c4.w; y2.w = cur.w * tw * tw;

            __stcs((float4*)(yp + pix), y2);
            __stcs((float4*)(cp + pix), c4);
        }
    }
}

// ---------------------------------------------------------------------------
// Persistent fused kernel: 296 co-resident CTAs walk the item list.
// ---------------------------------------------------------------------------
__global__ __launch_bounds__(256, 2) void fused_kernel(
    const float* __restrict__ x,
    const float* __restrict__ attn,
    float* __restrict__ out_y,
    float* __restrict__ out_c)
{
    __shared__ __align__(16) char smem_raw[4096];

    #pragma unroll 1
    for (int item = blockIdx.x; item < N_ITEMS; item += NCTA) {
        __syncthreads();   // smem reuse boundary between items

        int s = 0;
        #pragma unroll
        for (int i = 1; i < 16; i++)
            if (item >= c_seg_start[i]) s = i;
        const int u = item - c_seg_start[s];
        const int b = c_seg_b[s];

        if (c_seg_type[s] == 0)
            argmax_unit(x, b, u, smem_raw);
        else
            modulate_unit(x, attn, out_y, out_c, b, u, smem_raw);
    }
}

extern "C" void kernel_launch(void* const* d_in, const int* in_sizes, int n_in,
                              void* d_out, int out_size)
{
    const float* x    = (const float*)d_in[0];
    const float* attn = (const float*)d_in[1];
    float* out_y = (float*)d_out;
    float* out_c = (float*)d_out + (size_t)BC * PLANE;

    init_kernel<<<1, 32>>>();
    fused_kernel<<<NCTA, 256>>>(x, attn, out_y, out_c);
}

// round 12
// speedup vs baseline: 1.4429x; 1.3510x over previous
#include <cuda_runtime.h>
#include <cstdint>

#define B_  8
#define C_  19
#define H_  512
#define W_  512
#define PLANE (H_*W_)          // 262144
#define BC (B_*C_)             // 152

#define NA 512                 // argmax CTAs (64 strips x 8 batches)
#define NM 1216                // modulate CTAs (152 planes x 8)

__device__ float g_adjusted[BC * 4096];
__device__ int   g_done[B_];

__global__ void init_kernel() {
    if (threadIdx.x < B_) g_done[threadIdx.x] = 0;
}

// ---------------------------------------------------------------------------
// Argmax role (R6 config): CTA = one 8-row strip of one batch, 256 threads.
// t&127 = col quad (512 cols), t>>7 = 4-row half. __ldcs streaming reads.
// ---------------------------------------------------------------------------
__device__ __forceinline__ void argmax_role(const float* __restrict__ x,
                                            int bid, char* smem_raw)
{
    int (*hist)[20] = (int(*)[20])smem_raw;    // 64 x 20 ints = 5120B
    const int b     = bid >> 6;
    const int strip = bid & 63;
    const int t     = threadIdx.x;
    const int cq    = t & 127;
    const int rh    = t >> 7;

    for (int i = t; i < 64 * 20; i += 256) ((int*)hist)[i] = 0;
    __syncthreads();

    const float* xb = x + (size_t)b * C_ * PLANE
                        + ((size_t)strip * 8 + rh * 4) * W_ + cq * 4;
    const int blk = cq >> 1;

    #pragma unroll
    for (int r = 0; r < 4; r++) {
        const float* row = xb + r * W_;
        float4 bv = __ldcs((const float4*)row);
        int bx = 0, by = 0, bz = 0, bw = 0;
        #pragma unroll
        for (int c = 1; c < C_; c++) {
            float4 v = __ldcs((const float4*)(row + (size_t)c * PLANE));
            if (v.x > bv.x) { bv.x = v.x; bx = c; }
            if (v.y > bv.y) { bv.y = v.y; by = c; }
            if (v.z > bv.z) { bv.z = v.z; bz = c; }
            if (v.w > bv.w) { bv.w = v.w; bw = c; }
        }
        atomicAdd(&hist[blk][bx], 1);
        atomicAdd(&hist[blk][by], 1);
        atomicAdd(&hist[blk][bz], 1);
        atomicAdd(&hist[blk][bw], 1);
    }
    __syncthreads();

    for (int i = t; i < 64 * C_; i += 256) {
        int j = i / C_, c = i % C_;
        g_adjusted[((size_t)(b * C_ + c) * 64 + strip) * 64 + j] =
            (float)hist[j][c] * (1.0f / 64.0f);
    }

    __threadfence();      // release g_adjusted writes
    __syncthreads();
    if (t == 0) atomicAdd(&g_done[b], 1);
}

// ---------------------------------------------------------------------------
// Modulate role (R6 config): 8 CTAs per plane, forward batch order.
// Stages attn first (useful work), then waits for its batch's argmax.
// ---------------------------------------------------------------------------
__device__ __forceinline__ void modulate_role(const float* __restrict__ x,
                                              const float* __restrict__ attn,
                                              float* __restrict__ out_y,
                                              float* __restrict__ out_c,
                                              int mbid, char* smem_raw)
{
    float4* sm_attn = (float4*)smem_raw;       // 128 tiles x 16 floats = 8KB
    const int bc   = mbid >> 3;                // 0..151  (forward order)
    const int q    = mbid & 7;
    const int b    = bc / C_;
    const int tid  = threadIdx.x;
    const int mgrp = tid >> 6;
    const int quad = tid & 63;
    const int py   = quad >> 2;
    const int px0  = (quad & 3) << 2;

    // stage attn rows while the dependency may still be pending
    const float4* src = (const float4*)(attn + (size_t)bc * 1024 * 16) + q * 128 * 4;
    for (int i = tid; i < 128 * 4; i += 256) sm_attn[i] = src[i];

    // acquire: wait until all 64 argmax CTAs of batch b completed
    if (tid == 0) {
        while (((volatile int*)g_done)[b] < 64) __nanosleep(128);
        __threadfence();
    }
    __syncthreads();

    const float* adjc = g_adjusted + (size_t)bc * 4096;
    float4 pr[16];
    #pragma unroll
    for (int pi = 0; pi < 4; pi++)
        #pragma unroll
        for (int pj = 0; pj < 4; pj++)
            pr[pi * 4 + pj] =
                __ldcg((const float4*)(adjc + (pi * 16 + py) * 64 + pj * 16 + px0));

    const float* xp = x + (size_t)bc * PLANE;
    float*       yp = out_y + (size_t)bc * PLANE;
    float*       cp = out_c + (size_t)bc * PLANE;

    const int mh = q * 4 + mgrp;
    const int h  = mh * 16 + py;
    const size_t base = (size_t)h * W_ + px0;
    const int mlbase = mgrp * 32;

    #pragma unroll 1
    for (int ib = 0; ib < 32; ib += 4) {
        const size_t pix0 = base + (size_t)ib * 16;

        // 4 front-batched streaming loads (MLP_p1 = 4)
        float4 xq0 = __ldcs((const float4*)(xp + pix0));
        float4 xq1 = __ldcs((const float4*)(xp + pix0 + 16));
        float4 xq2 = __ldcs((const float4*)(xp + pix0 + 32));
        float4 xq3 = __ldcs((const float4*)(xp + pix0 + 48));

        #pragma unroll
        for (int j = 0; j < 4; j++) {
            const float4 cur = (j == 0) ? xq0 : (j == 1) ? xq1 : (j == 2) ? xq2 : xq3;
            const size_t pix = pix0 + (size_t)j * 16;
            const int mloc = mlbase + ib + j;

            float4 c4 = make_float4(0.f, 0.f, 0.f, 0.f);
            #pragma unroll
            for (int g = 0; g < 4; g++) {
                float4 a4 = sm_attn[mloc * 4 + g];
                c4.x = fmaf(a4.x, pr[g*4+0].x, c4.x);
                c4.y = fmaf(a4.x, pr[g*4+0].y, c4.y);
                c4.z = fmaf(a4.x, pr[g*4+0].z, c4.z);
                c4.w = fmaf(a4.x, pr[g*4+0].w, c4.w);
                c4.x = fmaf(a4.y, pr[g*4+1].x, c4.x);
                c4.y = fmaf(a4.y, pr[g*4+1].y, c4.y);
                c4.z = fmaf(a4.y, pr[g*4+1].z, c4.z);
                c4.w = fmaf(a4.y, pr[g*4+1].w, c4.w);
                c4.x = fmaf(a4.z, pr[g*4+2].x, c4.x);
                c4.y = fmaf(a4.z, pr[g*4+2].y, c4.y);
                c4.z = fmaf(a4.z, pr[g*4+2].z, c4.z);
                c4.w = fmaf(a4.z, pr[g*4+2].w, c4.w);
                c4.x = fmaf(a4.w, pr[g*4+3].x, c4.x);
                c4.y = fmaf(a4.w, pr[g*4+3].y, c4.y);
                c4.z = fmaf(a4.w, pr[g*4+3].z, c4.z);
                c4.w = fmaf(a4.w, pr[g*4+3].w, c4.w);
            }

            float4 y2;
            float tx = 1.f + c4.x; y2.x = cur.x * tx * tx;
            float ty = 1.f + c4.y; y2.y = cur.y * ty * ty;
            float tz = 1.f + c4.z; y2.z = cur.z * tz * tz;
            float tw = 1.f + c4.w; y2.w = cur.w * tw * tw;

            __stcs((float4*)(yp + pix), y2);
            __stcs((float4*)(cp + pix), c4);
        }
    }
}

// ---------------------------------------------------------------------------
// One launch: bids 0..511 argmax, 512..1727 modulate (forward batch order).
// ---------------------------------------------------------------------------
__global__ __launch_bounds__(256, 2) void fused_kernel(
    const float* __restrict__ x,
    const float* __restrict__ attn,
    float* __restrict__ out_y,
    float* __restrict__ out_c)
{
    __shared__ __align__(16) char smem_raw[8192];

    const int bid = blockIdx.x;
    if (bid < NA)
        argmax_role(x, bid, smem_raw);
    else
        modulate_role(x, attn, out_y, out_c, bid - NA, smem_raw);
}

extern "C" void kernel_launch(void* const* d_in, const int* in_sizes, int n_in,
                              void* d_out, int out_size)
{
    const float* x    = (const float*)d_in[0];
    const float* attn = (const float*)d_in[1];
    float* out_y = (float*)d_out;
    float* out_c = (float*)d_out + (size_t)BC * PLANE;

    init_kernel<<<1, 32>>>();
    fused_kernel<<<NA + NM, 256>>>(x, attn, out_y, out_c);
}

// round 13
// speedup vs baseline: 1.5122x; 1.0480x over previous
#include <cuda_runtime.h>
#include <cstdint>

#define B_  8
#define C_  19
#define H_  512
#define W_  512
#define PLANE (H_*W_)          // 262144
#define BC (B_*C_)             // 152

#define SEG 216                // CTAs per batch segment: 64 argmax + 152 modulate
#define NCTA (SEG * B_)        // 1728

__device__ float g_adjusted[BC * 4096];
__device__ int   g_done[B_];

__global__ void init_kernel() {
    if (threadIdx.x < B_) g_done[threadIdx.x] = 0;
}

// ---------------------------------------------------------------------------
// Argmax role: CTA = one 8-row strip of batch b, 256 threads.
// DEFAULT-policy loads: x[b] (19.9 MB) must stay L2-resident for M(b).
// ---------------------------------------------------------------------------
__device__ __forceinline__ void argmax_role(const float* __restrict__ x,
                                            int b, int strip, char* smem_raw)
{
    int (*hist)[20] = (int(*)[20])smem_raw;    // 64 x 20 ints
    const int t  = threadIdx.x;
    const int cq = t & 127;
    const int rh = t >> 7;

    for (int i = t; i < 64 * 20; i += 256) ((int*)hist)[i] = 0;
    __syncthreads();

    const float* xb = x + (size_t)b * C_ * PLANE
                        + ((size_t)strip * 8 + rh * 4) * W_ + cq * 4;
    const int blk = cq >> 1;

    #pragma unroll
    for (int r = 0; r < 4; r++) {
        const float* row = xb + r * W_;
        float4 bv = *(const float4*)row;
        int bx = 0, by = 0, bz = 0, bw = 0;
        #pragma unroll
        for (int c = 1; c < C_; c++) {
            float4 v = *(const float4*)(row + (size_t)c * PLANE);
            if (v.x > bv.x) { bv.x = v.x; bx = c; }
            if (v.y > bv.y) { bv.y = v.y; by = c; }
            if (v.z > bv.z) { bv.z = v.z; bz = c; }
            if (v.w > bv.w) { bv.w = v.w; bw = c; }
        }
        atomicAdd(&hist[blk][bx], 1);
        atomicAdd(&hist[blk][by], 1);
        atomicAdd(&hist[blk][bz], 1);
        atomicAdd(&hist[blk][bw], 1);
    }
    __syncthreads();

    for (int i = t; i < 64 * C_; i += 256) {
        int j = i / C_, c = i % C_;
        g_adjusted[((size_t)(b * C_ + c) * 64 + strip) * 64 + j] =
            (float)hist[j][c] * (1.0f / 64.0f);
    }

    __threadfence();      // release g_adjusted
    __syncthreads();
    if (t == 0) atomicAdd(&g_done[b], 1);
}

// ---------------------------------------------------------------------------
// Modulate role: w in [0,152): plane bc = b*19 + (w>>3), q = w&7.
// x via __ldcg (expects L2 hits on x[b] retained by A(b)), outputs __stcs.
// ---------------------------------------------------------------------------
__device__ __forceinline__ void modulate_role(const float* __restrict__ x,
                                              const float* __restrict__ attn,
                                              float* __restrict__ out_y,
                                              float* __restrict__ out_c,
                                              int b, int w, char* smem_raw)
{
    float4* sm_attn = (float4*)smem_raw;       // 128 tiles x 16 floats = 8KB
    const int bc   = b * C_ + (w >> 3);
    const int q    = w & 7;
    const int tid  = threadIdx.x;
    const int mgrp = tid >> 6;
    const int quad = tid & 63;
    const int py   = quad >> 2;
    const int px0  = (quad & 3) << 2;

    // stage attn rows while the dependency may still be pending
    const float4* src = (const float4*)(attn + (size_t)bc * 1024 * 16) + q * 128 * 4;
    for (int i = tid; i < 128 * 4; i += 256) sm_attn[i] = src[i];

    // acquire: all 64 argmax CTAs of batch b done
    if (tid == 0) {
        while (((volatile int*)g_done)[b] < 64) __nanosleep(128);
        __threadfence();
    }
    __syncthreads();

    const float* adjc = g_adjusted + (size_t)bc * 4096;
    float4 pr[16];
    #pragma unroll
    for (int pi = 0; pi < 4; pi++)
        #pragma unroll
        for (int pj = 0; pj < 4; pj++)
            pr[pi * 4 + pj] =
                __ldcg((const float4*)(adjc + (pi * 16 + py) * 64 + pj * 16 + px0));

    const float* xp = x + (size_t)bc * PLANE;
    float*       yp = out_y + (size_t)bc * PLANE;
    float*       cp = out_c + (size_t)bc * PLANE;

    const int mh = q * 4 + mgrp;
    const int h  = mh * 16 + py;
    const size_t base = (size_t)h * W_ + px0;
    const int mlbase = mgrp * 32;

    #pragma unroll 1
    for (int ib = 0; ib < 32; ib += 4) {
        const size_t pix0 = base + (size_t)ib * 16;

        // 4 front-batched loads (MLP_p1 = 4), L2-preferring
        float4 xq0 = __ldcg((const float4*)(xp + pix0));
        float4 xq1 = __ldcg((const float4*)(xp + pix0 + 16));
        float4 xq2 = __ldcg((const float4*)(xp + pix0 + 32));
        float4 xq3 = __ldcg((const float4*)(xp + pix0 + 48));

        #pragma unroll
        for (int j = 0; j < 4; j++) {
            const float4 cur = (j == 0) ? xq0 : (j == 1) ? xq1 : (j == 2) ? xq2 : xq3;
            const size_t pix = pix0 + (size_t)j * 16;
            const int mloc = mlbase + ib + j;

            float4 c4 = make_float4(0.f, 0.f, 0.f, 0.f);
            #pragma unroll
            for (int g = 0; g < 4; g++) {
                float4 a4 = sm_attn[mloc * 4 + g];
                c4.x = fmaf(a4.x, pr[g*4+0].x, c4.x);
                c4.y = fmaf(a4.x, pr[g*4+0].y, c4.y);
                c4.z = fmaf(a4.x, pr[g*4+0].z, c4.z);
                c4.w = fmaf(a4.x, pr[g*4+0].w, c4.w);
                c4.x = fmaf(a4.y, pr[g*4+1].x, c4.x);
                c4.y = fmaf(a4.y, pr[g*4+1].y, c4.y);
                c4.z = fmaf(a4.y, pr[g*4+1].z, c4.z);
                c4.w = fmaf(a4.y, pr[g*4+1].w, c4.w);
                c4.x = fmaf(a4.z, pr[g*4+2].x, c4.x);
                c4.y = fmaf(a4.z, pr[g*4+2].y, c4.y);
                c4.z = fmaf(a4.z, pr[g*4+2].z, c4.z);
                c4.w = fmaf(a4.z, pr[g*4+2].w, c4.w);
                c4.x = fmaf(a4.w, pr[g*4+3].x, c4.x);
                c4.y = fmaf(a4.w, pr[g*4+3].y, c4.y);
                c4.z = fmaf(a4.w, pr[g*4+3].z, c4.z);
                c4.w = fmaf(a4.w, pr[g*4+3].w, c4.w);
            }

            float4 y2;
            float tx = 1.f + c4.x; y2.x = cur.x * tx * tx;
            float ty = 1.f + c4.y; y2.y = cur.y * ty * ty;
            float tz = 1.f + c4.z; y2.z = cur.z * tz * tz;
            float tw = 1.f + c4.w; y2.w = cur.w * tw * tw;

            __stcs((float4*)(yp + pix), y2);
            __stcs((float4*)(cp + pix), c4);
        }
    }
}

// ---------------------------------------------------------------------------
// One launch, per-batch interleaved segments: [A(b):64][M(b):152] x 8.
// ---------------------------------------------------------------------------
__global__ __launch_bounds__(256, 2) void fused_kernel(
    const float* __restrict__ x,
    const float* __restrict__ attn,
    float* __restrict__ out_y,
    float* __restrict__ out_c)
{
    __shared__ __align__(16) char smem_raw[8192];

    const int b = blockIdx.x / SEG;
    const int u = blockIdx.x - b * SEG;

    if (u < 64)
        argmax_role(x, b, u, smem_raw);
    else
        modulate_role(x, attn, out_y, out_c, b, u - 64, smem_raw);
}

extern "C" void kernel_launch(void* const* d_in, const int* in_sizes, int n_in,
                              void* d_out, int out_size)
{
    const float* x    = (const float*)d_in[0];
    const float* attn = (const float*)d_in[1];
    float* out_y = (float*)d_out;
    float* out_c = (float*)d_out + (size_t)BC * PLANE;

    init_kernel<<<1, 32>>>();
    fused_kernel<<<NCTA, 256>>>(x, attn, out_y, out_c);
}

// round 14
// speedup vs baseline: 1.5344x; 1.0147x over previous
#include <cuda_runtime.h>
#include <cstdint>

#define B_  8
#define C_  19
#define H_  512
#define W_  512
#define PLANE (H_*W_)          // 262144
#define BC (B_*C_)             // 152

#define SEG 216                // per-batch segment: 64 argmax + 152 modulate
#define NCTA (SEG * B_)        // 1728

__device__ float g_adjusted[BC * 4096];
__device__ int   g_done[B_];     // argmax completion count (reset in-kernel)
__device__ int   g_mpass[B_];    // modulate acquire-passed count (reset in-kernel)

// ---------------------------------------------------------------------------
// Argmax role: CTA = one 8-row strip of batch b, 256 threads.
// DEFAULT-policy loads: x[b] (19.9 MB) must stay L2-resident for M(b).
// ---------------------------------------------------------------------------
__device__ __forceinline__ void argmax_role(const float* __restrict__ x,
                                            int b, int strip, char* smem_raw)
{
    int (*hist)[20] = (int(*)[20])smem_raw;    // 64 x 20 ints
    const int t  = threadIdx.x;
    const int cq = t & 127;
    const int rh = t >> 7;

    for (int i = t; i < 64 * 20; i += 256) ((int*)hist)[i] = 0;
    __syncthreads();

    const float* xb = x + (size_t)b * C_ * PLANE
                        + ((size_t)strip * 8 + rh * 4) * W_ + cq * 4;
    const int blk = cq >> 1;

    #pragma unroll
    for (int r = 0; r < 4; r++) {
        const float* row = xb + r * W_;
        float4 bv = *(const float4*)row;
        int bx = 0, by = 0, bz = 0, bw = 0;
        #pragma unroll
        for (int c = 1; c < C_; c++) {
            float4 v = *(const float4*)(row + (size_t)c * PLANE);
            if (v.x > bv.x) { bv.x = v.x; bx = c; }
            if (v.y > bv.y) { bv.y = v.y; by = c; }
            if (v.z > bv.z) { bv.z = v.z; bz = c; }
            if (v.w > bv.w) { bv.w = v.w; bw = c; }
        }
        atomicAdd(&hist[blk][bx], 1);
        atomicAdd(&hist[blk][by], 1);
        atomicAdd(&hist[blk][bz], 1);
        atomicAdd(&hist[blk][bw], 1);
    }
    __syncthreads();

    for (int i = t; i < 64 * C_; i += 256) {
        int j = i / C_, c = i % C_;
        g_adjusted[((size_t)(b * C_ + c) * 64 + strip) * 64 + j] =
            (float)hist[j][c] * (1.0f / 64.0f);
    }

    __threadfence();      // release g_adjusted
    __syncthreads();
    if (t == 0) atomicAdd(&g_done[b], 1);
}

// ---------------------------------------------------------------------------
// Modulate role: w in [0,152): plane bc = b*19 + (w>>3), q = w&7.
// x via __ldcg (L2 hits on x[b]), outputs __stcs. After acquire, the last
// of the 152 M(b) CTAs resets g_done[b]/g_mpass[b] for the next graph replay.
// ---------------------------------------------------------------------------
__device__ __forceinline__ void modulate_role(const float* __restrict__ x,
                                              const float* __restrict__ attn,
                                              float* __restrict__ out_y,
                                              float* __restrict__ out_c,
                                              int b, int w, char* smem_raw)
{
    float4* sm_attn = (float4*)smem_raw;       // 128 tiles x 16 floats = 8KB
    const int bc   = b * C_ + (w >> 3);
    const int q    = w & 7;
    const int tid  = threadIdx.x;
    const int mgrp = tid >> 6;
    const int quad = tid & 63;
    const int py   = quad >> 2;
    const int px0  = (quad & 3) << 2;

    // stage attn rows while the dependency may still be pending
    const float4* src = (const float4*)(attn + (size_t)bc * 1024 * 16) + q * 128 * 4;
    for (int i = tid; i < 128 * 4; i += 256) sm_attn[i] = src[i];

    // acquire: all 64 argmax CTAs of batch b done; then bump pass-count and
    // let the 152nd passer reset both counters (all waiters already passed).
    if (tid == 0) {
        while (((volatile int*)g_done)[b] < 64) __nanosleep(32);
        __threadfence();
        int p = atomicAdd(&g_mpass[b], 1);
        if (p == 151) {            // last M(b) CTA through the gate
            g_done[b]  = 0;
            g_mpass[b] = 0;
            __threadfence();
        }
    }
    __syncthreads();

    const float* adjc = g_adjusted + (size_t)bc * 4096;
    float4 pr[16];
    #pragma unroll
    for (int pi = 0; pi < 4; pi++)
        #pragma unroll
        for (int pj = 0; pj < 4; pj++)
            pr[pi * 4 + pj] =
                __ldcg((const float4*)(adjc + (pi * 16 + py) * 64 + pj * 16 + px0));

    const float* xp = x + (size_t)bc * PLANE;
    float*       yp = out_y + (size_t)bc * PLANE;
    float*       cp = out_c + (size_t)bc * PLANE;

    const int mh = q * 4 + mgrp;
    const int h  = mh * 16 + py;
    const size_t base = (size_t)h * W_ + px0;
    const int mlbase = mgrp * 32;

    #pragma unroll 1
    for (int ib = 0; ib < 32; ib += 4) {
        const size_t pix0 = base + (size_t)ib * 16;

        // 4 front-batched loads (MLP_p1 = 4), L2-preferring
        float4 xq0 = __ldcg((const float4*)(xp + pix0));
        float4 xq1 = __ldcg((const float4*)(xp + pix0 + 16));
        float4 xq2 = __ldcg((const float4*)(xp + pix0 + 32));
        float4 xq3 = __ldcg((const float4*)(xp + pix0 + 48));

        #pragma unroll
        for (int j = 0; j < 4; j++) {
            const float4 cur = (j == 0) ? xq0 : (j == 1) ? xq1 : (j == 2) ? xq2 : xq3;
            const size_t pix = pix0 + (size_t)j * 16;
            const int mloc = mlbase + ib + j;

            float4 c4 = make_float4(0.f, 0.f, 0.f, 0.f);
            #pragma unroll
            for (int g = 0; g < 4; g++) {
                float4 a4 = sm_attn[mloc * 4 + g];
                c4.x = fmaf(a4.x, pr[g*4+0].x, c4.x);
                c4.y = fmaf(a4.x, pr[g*4+0].y, c4.y);
                c4.z = fmaf(a4.x, pr[g*4+0].z, c4.z);
                c4.w = fmaf(a4.x, pr[g*4+0].w, c4.w);
                c4.x = fmaf(a4.y, pr[g*4+1].x, c4.x);
                c4.y = fmaf(a4.y, pr[g*4+1].y, c4.y);
                c4.z = fmaf(a4.y, pr[g*4+1].z, c4.z);
                c4.w = fmaf(a4.y, pr[g*4+1].w, c4.w);
                c4.x = fmaf(a4.z, pr[g*4+2].x, c4.x);
                c4.y = fmaf(a4.z, pr[g*4+2].y, c4.y);
                c4.z = fmaf(a4.z, pr[g*4+2].z, c4.z);
                c4.w = fmaf(a4.z, pr[g*4+2].w, c4.w);
                c4.x = fmaf(a4.w, pr[g*4+3].x, c4.x);
                c4.y = fmaf(a4.w, pr[g*4+3].y, c4.y);
                c4.z = fmaf(a4.w, pr[g*4+3].z, c4.z);
                c4.w = fmaf(a4.w, pr[g*4+3].w, c4.w);
            }

            float4 y2;
            float tx = 1.f + c4.x; y2.x = cur.x * tx * tx;
            float ty = 1.f + c4.y; y2.y = cur.y * ty * ty;
            float tz = 1.f + c4.z; y2.z = cur.z * tz * tz;
            float tw = 1.f + c4.w; y2.w = cur.w * tw * tw;

            __stcs((float4*)(yp + pix), y2);
            __stcs((float4*)(cp + pix), c4);
        }
    }
}

// ---------------------------------------------------------------------------
// One launch, per-batch interleaved segments: [A(b):64][M(b):152] x 8.
// Counters self-reset each run (device globals are 0 at module load).
// ---------------------------------------------------------------------------
__global__ __launch_bounds__(256, 2) void fused_kernel(
    const float* __restrict__ x,
    const float* __restrict__ attn,
    float* __restrict__ out_y,
    float* __restrict__ out_c)
{
    __shared__ __align__(16) char smem_raw[8192];

    const int b = blockIdx.x / SEG;
    const int u = blockIdx.x - b * SEG;

    if (u < 64)
        argmax_role(x, b, u, smem_raw);
    else
        modulate_role(x, attn, out_y, out_c, b, u - 64, smem_raw);
}

extern "C" void kernel_launch(void* const* d_in, const int* in_sizes, int n_in,
                              void* d_out, int out_size)
{
    const float* x    = (const float*)d_in[0];
    const float* attn = (const float*)d_in[1];
    float* out_y = (float*)d_out;
    float* out_c = (float*)d_out + (size_t)BC * PLANE;

    fused_kernel<<<NCTA, 256>>>(x, attn, out_y, out_c);
}